// round 1
// baseline (speedup 1.0000x reference)
#include <cuda_runtime.h>

#define EPS  1e-6f
#define DD   256     // in_features
#define BM   64      // batch tile
#define BN   64      // K tile
#define DK   32      // depth chunk
#define LDT  68      // padded second dim of transposed smem tiles

// Fused hyperbolic MLR logits.
// out[b,k] = lam_k * na_k * asinh( 2*za / ((1-z2)*na_k + EPS) )
// where all per-(b,k) terms are built from xp=<x,p>, xa=<x,a>, x2, p2, <p,a>, ||a||^2.
__global__ __launch_bounds__(256)
void hyp_mlr_kernel(const float* __restrict__ x,
                    const float* __restrict__ p,
                    const float* __restrict__ a,
                    float* __restrict__ out, int K)
{
    // transposed tiles: [d][row] so inner loop reads are LDS.128, conflict-free
    __shared__ float xs[DK][LDT];
    __shared__ float ps[DK][LDT];
    __shared__ float as_[DK][LDT];
    __shared__ float p2s[BN], pas[BN], na2s[BN], x2s[BM];

    const int tid = threadIdx.x;
    const int b0  = blockIdx.y * BM;
    const int k0  = blockIdx.x * BN;

    // ---------------- per-k / per-b stats (redundant per block, but tiny) ---
    {
        const int g   = tid >> 2;   // 0..63 : which row (k or b)
        const int sub = tid & 3;    // 0..3  : which quarter of D

        const float4* prow = (const float4*)(p + (size_t)(k0 + g) * DD) + sub * 16;
        const float4* arow = (const float4*)(a + (size_t)(k0 + g) * DD) + sub * 16;
        float p2 = 0.f, pa = 0.f, na2 = 0.f;
        #pragma unroll
        for (int i = 0; i < 16; i++) {
            float4 pv = prow[i];
            float4 av = arow[i];
            p2  += pv.x*pv.x + pv.y*pv.y + pv.z*pv.z + pv.w*pv.w;
            pa  += pv.x*av.x + pv.y*av.y + pv.z*av.z + pv.w*av.w;
            na2 += av.x*av.x + av.y*av.y + av.z*av.z + av.w*av.w;
        }
        p2  += __shfl_xor_sync(0xffffffffu, p2, 1);
        p2  += __shfl_xor_sync(0xffffffffu, p2, 2);
        pa  += __shfl_xor_sync(0xffffffffu, pa, 1);
        pa  += __shfl_xor_sync(0xffffffffu, pa, 2);
        na2 += __shfl_xor_sync(0xffffffffu, na2, 1);
        na2 += __shfl_xor_sync(0xffffffffu, na2, 2);
        if (sub == 0) { p2s[g] = p2; pas[g] = pa; na2s[g] = na2; }

        const float4* xrow = (const float4*)(x + (size_t)(b0 + g) * DD) + sub * 16;
        float x2 = 0.f;
        #pragma unroll
        for (int i = 0; i < 16; i++) {
            float4 xv = xrow[i];
            x2 += xv.x*xv.x + xv.y*xv.y + xv.z*xv.z + xv.w*xv.w;
        }
        x2 += __shfl_xor_sync(0xffffffffu, x2, 1);
        x2 += __shfl_xor_sync(0xffffffffu, x2, 2);
        if (sub == 0) x2s[g] = x2;
    }

    // ---------------- dual GEMM mainloop: accp = x.p^T, acca = x.a^T --------
    float accp[4][4] = {}, acca[4][4] = {};
    const int ty = tid >> 4;   // 0..15 -> 4 batch rows each
    const int tx = tid & 15;   // 0..15 -> 4 k cols each

    for (int d0 = 0; d0 < DD; d0 += DK) {
        __syncthreads();  // previous-iter reads done (also fences stats on iter 0)
        #pragma unroll
        for (int v = 0; v < 2; v++) {
            int f   = v * 256 + tid;   // float4 id within 64x32 tile
            int row = f >> 3;          // 0..63
            int c4  = f & 7;           // 0..7  -> d offset c4*4
            float4 xv = *(const float4*)(x + (size_t)(b0 + row) * DD + d0 + c4 * 4);
            float4 pv = *(const float4*)(p + (size_t)(k0 + row) * DD + d0 + c4 * 4);
            float4 av = *(const float4*)(a + (size_t)(k0 + row) * DD + d0 + c4 * 4);
            xs [c4*4+0][row] = xv.x; xs [c4*4+1][row] = xv.y;
            xs [c4*4+2][row] = xv.z; xs [c4*4+3][row] = xv.w;
            ps [c4*4+0][row] = pv.x; ps [c4*4+1][row] = pv.y;
            ps [c4*4+2][row] = pv.z; ps [c4*4+3][row] = pv.w;
            as_[c4*4+0][row] = av.x; as_[c4*4+1][row] = av.y;
            as_[c4*4+2][row] = av.z; as_[c4*4+3][row] = av.w;
        }
        __syncthreads();

        #pragma unroll
        for (int kk = 0; kk < DK; kk++) {
            float4 xf = *(const float4*)&xs [kk][ty * 4];
            float4 pf = *(const float4*)&ps [kk][tx * 4];
            float4 af = *(const float4*)&as_[kk][tx * 4];
            float xr[4] = {xf.x, xf.y, xf.z, xf.w};
            float pr[4] = {pf.x, pf.y, pf.z, pf.w};
            float ar[4] = {af.x, af.y, af.z, af.w};
            #pragma unroll
            for (int i = 0; i < 4; i++)
                #pragma unroll
                for (int j = 0; j < 4; j++) {
                    accp[i][j] += xr[i] * pr[j];
                    acca[i][j] += xr[i] * ar[j];
                }
        }
    }

    // ---------------- epilogue: hyperbolic MLR logit -------------------------
    #pragma unroll
    for (int i = 0; i < 4; i++) {
        int   b  = b0 + ty * 4 + i;
        float x2 = x2s[ty * 4 + i];
        float4 res;
        float* r = (float*)&res;
        #pragma unroll
        for (int j = 0; j < 4; j++) {
            int   kc  = tx * 4 + j;
            float p2  = p2s[kc];
            float pa  = pas[kc];
            float na2 = na2s[kc];
            float xp  = accp[i][j];
            float xa  = acca[i][j];

            float beta  = 1.f - p2;                               // 1 - ||p||^2
            float alpha = -(1.f - 2.f * xp + x2);                 // -(1+2uv+v2)
            float den   = 1.f - 2.f * xp + p2 * x2 + EPS;         // mobius denom + eps
            float inv   = 1.f / den;
            float z2 = (alpha*alpha*p2 + 2.f*alpha*beta*xp + beta*beta*x2) * inv * inv;
            float za = beta * (alpha * pa + beta * xa) * inv;     // <z, a_pt>
            float na = beta * sqrtf(na2);                          // ||a_pt||
            float lam = 2.f / (beta + EPS);                        // conformal factor
            float t = 2.f * za / ((1.f - z2) * na + EPS);
            r[j] = lam * na * asinhf(t);
        }
        *(float4*)(out + (size_t)b * K + k0 + tx * 4) = res;
    }
}

extern "C" void kernel_launch(void* const* d_in, const int* in_sizes, int n_in,
                              void* d_out, int out_size)
{
    const float* x = (const float*)d_in[0];
    const float* p = (const float*)d_in[1];
    const float* a = (const float*)d_in[2];
    float* out = (float*)d_out;

    const int B = in_sizes[0] / DD;   // 512
    const int K = in_sizes[1] / DD;   // 1024

    dim3 grid(K / BN, B / BM);        // (16, 8) = 128 blocks
    hyp_mlr_kernel<<<grid, 256>>>(x, p, a, out, K);
}

// round 2
// speedup vs baseline: 1.1317x; 1.1317x over previous
#include <cuda_runtime.h>

#define EPS  1e-6f
#define DD   256     // in_features
#define BM   64      // batch tile
#define BN   64      // K tile
#define DK   32      // depth chunk
#define LDT  68      // padded second dim of transposed smem tiles
#define NIT  (DD / DK)

// packed fp32x2 FMA (Blackwell FFMA2) — only reachable via PTX
__device__ __forceinline__ void ffma2(unsigned long long& d,
                                      unsigned long long a,
                                      unsigned long long b) {
    asm("fma.rn.f32x2 %0, %1, %2, %3;" : "=l"(d) : "l"(a), "l"(b), "l"(d));
}
__device__ __forceinline__ unsigned long long bcast2(float v) {
    unsigned long long r;
    asm("mov.b64 %0, {%1, %1};" : "=l"(r) : "r"(__float_as_uint(v)));
    return r;
}
#define LO32F(u) __uint_as_float((unsigned)(u))
#define HI32F(u) __uint_as_float((unsigned)((u) >> 32))

// Fused hyperbolic MLR logits:
// out[b,k] = lam_k * na_k * asinh( 2*za / ((1-z2)*na_k + EPS) )
// built from xp=<x,p>, xa=<x,a>, x2, p2, <p,a>, ||a||^2 (no [B,K,D] intermediate).
__global__ __launch_bounds__(256)
void hyp_mlr_kernel(const float* __restrict__ x,
                    const float* __restrict__ p,
                    const float* __restrict__ a,
                    float* __restrict__ out, int K)
{
    // transposed tiles [d][col], col XOR-swizzled by (d>>2)&7 at float4 grain
    __shared__ float xs[DK][LDT];
    __shared__ float ps[DK][LDT];
    __shared__ float as_[DK][LDT];
    __shared__ float p2s[BN], pas[BN], na2s[BN], x2s[BM];

    const int tid = threadIdx.x;
    const int b0  = blockIdx.y * BM;
    const int k0  = blockIdx.x * BN;

    // ---------------- per-k / per-b stats ------------------------------------
    {
        const int g   = tid >> 2;   // row (k or b)
        const int sub = tid & 3;    // quarter of D

        const float4* prow = (const float4*)(p + (size_t)(k0 + g) * DD) + sub * 16;
        const float4* arow = (const float4*)(a + (size_t)(k0 + g) * DD) + sub * 16;
        float p2 = 0.f, pa = 0.f, na2 = 0.f;
        #pragma unroll
        for (int i = 0; i < 16; i++) {
            float4 pv = prow[i];
            float4 av = arow[i];
            p2  += pv.x*pv.x + pv.y*pv.y + pv.z*pv.z + pv.w*pv.w;
            pa  += pv.x*av.x + pv.y*av.y + pv.z*av.z + pv.w*av.w;
            na2 += av.x*av.x + av.y*av.y + av.z*av.z + av.w*av.w;
        }
        p2  += __shfl_xor_sync(0xffffffffu, p2, 1);
        p2  += __shfl_xor_sync(0xffffffffu, p2, 2);
        pa  += __shfl_xor_sync(0xffffffffu, pa, 1);
        pa  += __shfl_xor_sync(0xffffffffu, pa, 2);
        na2 += __shfl_xor_sync(0xffffffffu, na2, 1);
        na2 += __shfl_xor_sync(0xffffffffu, na2, 2);
        if (sub == 0) { p2s[g] = p2; pas[g] = pa; na2s[g] = na2; }

        const float4* xrow = (const float4*)(x + (size_t)(b0 + g) * DD) + sub * 16;
        float x2 = 0.f;
        #pragma unroll
        for (int i = 0; i < 16; i++) {
            float4 xv = xrow[i];
            x2 += xv.x*xv.x + xv.y*xv.y + xv.z*xv.z + xv.w*xv.w;
        }
        x2 += __shfl_xor_sync(0xffffffffu, x2, 1);
        x2 += __shfl_xor_sync(0xffffffffu, x2, 2);
        if (sub == 0) x2s[g] = x2;
    }

    // ---------------- dual GEMM mainloop (FFMA2) -----------------------------
    unsigned long long accp2[4][2] = {}, acca2[4][2] = {};
    const int ty = tid >> 4;   // 0..15 -> 4 batch rows
    const int tx = tid & 15;   // 0..15 -> 4 k cols

    // global staging regs (prefetch pipeline)
    float4 gx[2], gp[2], ga[2];
    #pragma unroll
    for (int v = 0; v < 2; v++) {
        int f   = v * 256 + tid;
        int row = f >> 3;
        int c4  = f & 7;
        gx[v] = *(const float4*)(x + (size_t)(b0 + row) * DD + c4 * 4);
        gp[v] = *(const float4*)(p + (size_t)(k0 + row) * DD + c4 * 4);
        ga[v] = *(const float4*)(a + (size_t)(k0 + row) * DD + c4 * 4);
    }

    for (int it = 0; it < NIT; it++) {
        // store staged regs -> smem, transposed + swizzled (conflict-free)
        #pragma unroll
        for (int v = 0; v < 2; v++) {
            int f   = v * 256 + tid;
            int row = f >> 3;          // 0..63
            int c4  = f & 7;           // d group; swizzle s(d) = (d>>2)&7 = c4
            int col = (((row >> 2) ^ c4) << 2) | (row & 3);
            xs [c4*4+0][col] = gx[v].x; xs [c4*4+1][col] = gx[v].y;
            xs [c4*4+2][col] = gx[v].z; xs [c4*4+3][col] = gx[v].w;
            ps [c4*4+0][col] = gp[v].x; ps [c4*4+1][col] = gp[v].y;
            ps [c4*4+2][col] = gp[v].z; ps [c4*4+3][col] = gp[v].w;
            as_[c4*4+0][col] = ga[v].x; as_[c4*4+1][col] = ga[v].y;
            as_[c4*4+2][col] = ga[v].z; as_[c4*4+3][col] = ga[v].w;
        }
        __syncthreads();

        // prefetch next chunk while computing this one
        if (it + 1 < NIT) {
            int d0n = (it + 1) * DK;
            #pragma unroll
            for (int v = 0; v < 2; v++) {
                int f   = v * 256 + tid;
                int row = f >> 3;
                int c4  = f & 7;
                gx[v] = *(const float4*)(x + (size_t)(b0 + row) * DD + d0n + c4 * 4);
                gp[v] = *(const float4*)(p + (size_t)(k0 + row) * DD + d0n + c4 * 4);
                ga[v] = *(const float4*)(a + (size_t)(k0 + row) * DD + d0n + c4 * 4);
            }
        }

        #pragma unroll
        for (int kk = 0; kk < DK; kk++) {
            const int sk = (kk >> 2) & 7;
            float4 xf = *(const float4*)&xs[kk][(ty ^ sk) << 2];
            ulonglong2 pf = *(const ulonglong2*)&ps [kk][(tx ^ sk) << 2];
            ulonglong2 af = *(const ulonglong2*)&as_[kk][(tx ^ sk) << 2];
            unsigned long long xb[4];
            xb[0] = bcast2(xf.x); xb[1] = bcast2(xf.y);
            xb[2] = bcast2(xf.z); xb[3] = bcast2(xf.w);
            #pragma unroll
            for (int i = 0; i < 4; i++) {
                ffma2(accp2[i][0], xb[i], pf.x);
                ffma2(accp2[i][1], xb[i], pf.y);
                ffma2(acca2[i][0], xb[i], af.x);
                ffma2(acca2[i][1], xb[i], af.y);
            }
        }
        __syncthreads();
    }

    // ---------------- epilogue: hyperbolic MLR logit -------------------------
    #pragma unroll
    for (int i = 0; i < 4; i++) {
        int   b  = b0 + ty * 4 + i;
        float x2 = x2s[ty * 4 + i];
        float4 res;
        float* r = (float*)&res;
        float xpv[4] = { LO32F(accp2[i][0]), HI32F(accp2[i][0]),
                         LO32F(accp2[i][1]), HI32F(accp2[i][1]) };
        float xav[4] = { LO32F(acca2[i][0]), HI32F(acca2[i][0]),
                         LO32F(acca2[i][1]), HI32F(acca2[i][1]) };
        #pragma unroll
        for (int j = 0; j < 4; j++) {
            int   kc  = tx * 4 + j;
            float p2  = p2s[kc];
            float pa  = pas[kc];
            float na2 = na2s[kc];
            float xp  = xpv[j];
            float xa  = xav[j];

            float beta  = 1.f - p2;                       // 1 - ||p||^2
            float alpha = -(1.f - 2.f * xp + x2);         // -(1+2uv+v2)
            float den   = 1.f - 2.f * xp + p2 * x2 + EPS; // mobius denom + eps
            float inv   = 1.f / den;
            float z2 = (alpha*alpha*p2 + 2.f*alpha*beta*xp + beta*beta*x2) * inv * inv;
            float za = beta * (alpha * pa + beta * xa) * inv;  // <z, a_pt>
            float na = beta * sqrtf(na2);                       // ||a_pt||
            float lam = 2.f / (beta + EPS);                     // conformal factor
            float t = 2.f * za / ((1.f - z2) * na + EPS);
            r[j] = lam * na * asinhf(t);
        }
        *(float4*)(out + (size_t)b * K + k0 + tx * 4) = res;
    }
}

extern "C" void kernel_launch(void* const* d_in, const int* in_sizes, int n_in,
                              void* d_out, int out_size)
{
    const float* x = (const float*)d_in[0];
    const float* p = (const float*)d_in[1];
    const float* a = (const float*)d_in[2];
    float* out = (float*)d_out;

    const int B = in_sizes[0] / DD;   // 512
    const int K = in_sizes[1] / DD;   // 1024

    dim3 grid(K / BN, B / BM);        // (16, 8) = 128 blocks
    hyp_mlr_kernel<<<grid, 256>>>(x, p, a, out, K);
}